// round 2
// baseline (speedup 1.0000x reference)
#include <cuda_runtime.h>

#define N_NODES   1048576
#define N_GRAPHS  1024
#define F_X       128
#define F_U       128
#define F_CAT     256
#define HIDDEN    512
#define F_OUT     128

// Scratch (allocation-free rule: __device__ globals)
__device__ int   g_offsets[N_GRAPHS + 1];
__device__ float g_concat[N_GRAPHS * F_CAT];   // [1024, 256] = x_agg || u
__device__ float g_h[N_GRAPHS * HIDDEN];       // [1024, 512]

// ---------------------------------------------------------------------------
// 1) Find segment boundaries from the sorted batch vector (int32 on device).
//    g_offsets[g] = first node index with batch >= g; g_offsets[N_GRAPHS] = N.
//    Handles empty graphs (consecutive equal offsets). Clamped scatter range.
// ---------------------------------------------------------------------------
__global__ void boundaries_kernel(const int* __restrict__ batch) {
    int i = blockIdx.x * blockDim.x + threadIdx.x;
    if (i >= N_NODES) return;
    int b = batch[i];
    int prev = (i == 0) ? -1 : batch[i - 1];
    // clamp defensively so bad values can never write OOB
    int lo = prev + 1; if (lo < 0) lo = 0;
    int hi = b;        if (hi > N_GRAPHS) hi = N_GRAPHS;
    for (int g = lo; g <= hi; g++) g_offsets[g] = i;
    if (i == N_NODES - 1) {
        int lo2 = b + 1; if (lo2 < 0) lo2 = 0;
        for (int g = lo2; g <= N_GRAPHS; g++) g_offsets[g] = N_NODES;
    }
}

// ---------------------------------------------------------------------------
// 2) Segment mean of x over each graph's contiguous node range, written to
//    g_concat[:, 0:128]; u copied to g_concat[:, 128:256].
//    512 threads = 16 row-groups x 32 lanes; lane l owns features [4l, 4l+4).
//    float4 loads -> 512B coalesced per row per warp; 4 loads in flight.
// ---------------------------------------------------------------------------
__global__ void __launch_bounds__(512) seg_mean_kernel(const float* __restrict__ x,
                                                       const float* __restrict__ u) {
    const int g     = blockIdx.x;
    const int start = g_offsets[g];
    const int end   = g_offsets[g + 1];
    const int tid   = threadIdx.x;
    const int lane  = tid & 31;   // feature group
    const int grp   = tid >> 5;   // row group 0..15

    const float* xb = x + (size_t)lane * 4;

    float4 a0 = {0,0,0,0}, a1 = {0,0,0,0}, a2 = {0,0,0,0}, a3 = {0,0,0,0};
    int r = start + grp;
    for (; r + 48 < end; r += 64) {
        float4 v0 = *(const float4*)(xb + (size_t)(r     ) * F_X);
        float4 v1 = *(const float4*)(xb + (size_t)(r + 16) * F_X);
        float4 v2 = *(const float4*)(xb + (size_t)(r + 32) * F_X);
        float4 v3 = *(const float4*)(xb + (size_t)(r + 48) * F_X);
        a0.x += v0.x; a0.y += v0.y; a0.z += v0.z; a0.w += v0.w;
        a1.x += v1.x; a1.y += v1.y; a1.z += v1.z; a1.w += v1.w;
        a2.x += v2.x; a2.y += v2.y; a2.z += v2.z; a2.w += v2.w;
        a3.x += v3.x; a3.y += v3.y; a3.z += v3.z; a3.w += v3.w;
    }
    for (; r < end; r += 16) {
        float4 v = *(const float4*)(xb + (size_t)r * F_X);
        a0.x += v.x; a0.y += v.y; a0.z += v.z; a0.w += v.w;
    }
    a0.x += a1.x + a2.x + a3.x;
    a0.y += a1.y + a2.y + a3.y;
    a0.z += a1.z + a2.z + a3.z;
    a0.w += a1.w + a2.w + a3.w;

    __shared__ float4 sm[16][32];
    sm[grp][lane] = a0;
    __syncthreads();
    #pragma unroll
    for (int s = 8; s > 0; s >>= 1) {
        if (grp < s) {
            float4 a = sm[grp][lane];
            float4 b = sm[grp + s][lane];
            a.x += b.x; a.y += b.y; a.z += b.z; a.w += b.w;
            sm[grp][lane] = a;
        }
        __syncthreads();
    }

    if (grp == 0) {
        int cnt = end - start;
        float inv = (cnt > 0) ? (1.0f / (float)cnt) : 0.0f;
        float4 a = sm[0][lane];
        a.x *= inv; a.y *= inv; a.z *= inv; a.w *= inv;
        *(float4*)(g_concat + (size_t)g * F_CAT + lane * 4) = a;
    } else if (grp == 1) {
        float4 v = *(const float4*)(u + (size_t)g * F_U + lane * 4);
        *(float4*)(g_concat + (size_t)g * F_CAT + F_X + lane * 4) = v;
    }
}

// ---------------------------------------------------------------------------
// 3) Tiled SIMT GEMM: C[M,N] = act(A[M,K] @ B[K,N] + bias).
//    BM=BN=64, BK=16, 256 threads, 4x4 micro-tile per thread.
//    All problem dims divide the tiles exactly (M=1024; N=512/128; K=256/512).
// ---------------------------------------------------------------------------
template <int K, bool RELU>
__global__ void __launch_bounds__(256) gemm_kernel(const float* __restrict__ A,
                                                   const float* __restrict__ B,
                                                   const float* __restrict__ bias,
                                                   float* __restrict__ C, int N) {
    const int BM = 64, BN = 64, BK = 16;
    __shared__ float As[BK][BM + 1];  // +1 pad: conflict-free transposed store
    __shared__ float Bs[BK][BN];

    const int bm  = blockIdx.y * BM;
    const int bn  = blockIdx.x * BN;
    const int tid = threadIdx.x;
    const int tx  = tid & 15;
    const int ty  = tid >> 4;

    float acc[4][4] = {};

    for (int k0 = 0; k0 < K; k0 += BK) {
        #pragma unroll
        for (int i = 0; i < 4; i++) {          // A tile: 64x16
            int idx = tid + 256 * i;
            int row = idx >> 4, col = idx & 15;
            As[col][row] = A[(size_t)(bm + row) * K + k0 + col];
        }
        #pragma unroll
        for (int i = 0; i < 4; i++) {          // B tile: 16x64
            int idx = tid + 256 * i;
            int row = idx >> 6, col = idx & 63;
            Bs[row][col] = B[(size_t)(k0 + row) * N + bn + col];
        }
        __syncthreads();

        #pragma unroll
        for (int k = 0; k < BK; k++) {
            float a[4], b[4];
            #pragma unroll
            for (int i = 0; i < 4; i++) a[i] = As[k][ty * 4 + i];
            #pragma unroll
            for (int j = 0; j < 4; j++) b[j] = Bs[k][tx * 4 + j];
            #pragma unroll
            for (int i = 0; i < 4; i++)
                #pragma unroll
                for (int j = 0; j < 4; j++)
                    acc[i][j] = fmaf(a[i], b[j], acc[i][j]);
        }
        __syncthreads();
    }

    #pragma unroll
    for (int i = 0; i < 4; i++) {
        int row = bm + ty * 4 + i;
        #pragma unroll
        for (int j = 0; j < 4; j++) {
            int col = bn + tx * 4 + j;
            float v = acc[i][j] + bias[col];
            if (RELU) v = fmaxf(v, 0.0f);
            C[(size_t)row * N + col] = v;
        }
    }
}

// ---------------------------------------------------------------------------
// Launch. Inputs (metadata order): x, edge_index, edge_attr, u, batch,
//                                  W1, b1, W2, b2.  edge_* are unused.
//                                  int64 inputs arrive as int32 on device.
// ---------------------------------------------------------------------------
extern "C" void kernel_launch(void* const* d_in, const int* in_sizes, int n_in,
                              void* d_out, int out_size) {
    const float* x     = (const float*)d_in[0];
    const float* u     = (const float*)d_in[3];
    const int*   batch = (const int*)d_in[4];
    const float* W1    = (const float*)d_in[5];
    const float* b1    = (const float*)d_in[6];
    const float* W2    = (const float*)d_in[7];
    const float* b2    = (const float*)d_in[8];
    float*       out   = (float*)d_out;

    void* p_concat = nullptr;
    void* p_h      = nullptr;
    cudaGetSymbolAddress(&p_concat, g_concat);  // not a stream op: capture-safe
    cudaGetSymbolAddress(&p_h, g_h);

    boundaries_kernel<<<(N_NODES + 255) / 256, 256>>>(batch);
    seg_mean_kernel<<<N_GRAPHS, 512>>>(x, u);
    gemm_kernel<F_CAT,  true ><<<dim3(HIDDEN / 64, N_GRAPHS / 64), 256>>>(
        (const float*)p_concat, W1, b1, (float*)p_h, HIDDEN);
    gemm_kernel<HIDDEN, false><<<dim3(F_OUT / 64, N_GRAPHS / 64), 256>>>(
        (const float*)p_h, W2, b2, out, F_OUT);
}

// round 3
// speedup vs baseline: 1.2161x; 1.2161x over previous
#include <cuda_runtime.h>

#define N_NODES   1048576
#define N_GRAPHS  1024
#define F_X       128
#define F_U       128
#define F_CAT     256
#define HIDDEN    512
#define F_OUT     128

// Scratch (allocation-free rule: __device__ globals)
__device__ int   g_offsets[N_GRAPHS + 1];
__device__ float g_concat[N_GRAPHS * F_CAT];   // [1024, 256] = x_agg || u
__device__ float g_h[N_GRAPHS * HIDDEN];       // [1024, 512]

// ---------------------------------------------------------------------------
// 1) Segment boundaries from the sorted batch vector (int32 on device).
// ---------------------------------------------------------------------------
__global__ void boundaries_kernel(const int* __restrict__ batch) {
    int i = blockIdx.x * blockDim.x + threadIdx.x;
    if (i >= N_NODES) return;
    int b = batch[i];
    int prev = (i == 0) ? -1 : batch[i - 1];
    int lo = prev + 1; if (lo < 0) lo = 0;
    int hi = b;        if (hi > N_GRAPHS) hi = N_GRAPHS;
    for (int g = lo; g <= hi; g++) g_offsets[g] = i;
    if (i == N_NODES - 1) {
        int lo2 = b + 1; if (lo2 < 0) lo2 = 0;
        for (int g = lo2; g <= N_GRAPHS; g++) g_offsets[g] = N_NODES;
    }
}

// ---------------------------------------------------------------------------
// 2) Segment mean of x -> g_concat[:,0:128]; u -> g_concat[:,128:256].
//    One block per graph; 512 threads = 16 row-groups x 32 lanes.
//    Streaming loads (__ldcs): x is 512MB read-once, keep it out of L2.
// ---------------------------------------------------------------------------
__global__ void __launch_bounds__(512) seg_mean_kernel(const float* __restrict__ x,
                                                       const float* __restrict__ u) {
    const int g     = blockIdx.x;
    const int start = g_offsets[g];
    const int end   = g_offsets[g + 1];
    const int tid   = threadIdx.x;
    const int lane  = tid & 31;   // feature group
    const int grp   = tid >> 5;   // row group 0..15

    const float* xb = x + (size_t)lane * 4;

    float4 a0 = {0,0,0,0}, a1 = {0,0,0,0}, a2 = {0,0,0,0}, a3 = {0,0,0,0};
    int r = start + grp;
    for (; r + 48 < end; r += 64) {
        float4 v0 = __ldcs((const float4*)(xb + (size_t)(r     ) * F_X));
        float4 v1 = __ldcs((const float4*)(xb + (size_t)(r + 16) * F_X));
        float4 v2 = __ldcs((const float4*)(xb + (size_t)(r + 32) * F_X));
        float4 v3 = __ldcs((const float4*)(xb + (size_t)(r + 48) * F_X));
        a0.x += v0.x; a0.y += v0.y; a0.z += v0.z; a0.w += v0.w;
        a1.x += v1.x; a1.y += v1.y; a1.z += v1.z; a1.w += v1.w;
        a2.x += v2.x; a2.y += v2.y; a2.z += v2.z; a2.w += v2.w;
        a3.x += v3.x; a3.y += v3.y; a3.z += v3.z; a3.w += v3.w;
    }
    for (; r < end; r += 16) {
        float4 v = __ldcs((const float4*)(xb + (size_t)r * F_X));
        a0.x += v.x; a0.y += v.y; a0.z += v.z; a0.w += v.w;
    }
    a0.x += a1.x + a2.x + a3.x;
    a0.y += a1.y + a2.y + a3.y;
    a0.z += a1.z + a2.z + a3.z;
    a0.w += a1.w + a2.w + a3.w;

    __shared__ float4 sm[16][32];
    sm[grp][lane] = a0;
    __syncthreads();
    #pragma unroll
    for (int s = 8; s > 0; s >>= 1) {
        if (grp < s) {
            float4 a = sm[grp][lane];
            float4 b = sm[grp + s][lane];
            a.x += b.x; a.y += b.y; a.z += b.z; a.w += b.w;
            sm[grp][lane] = a;
        }
        __syncthreads();
    }

    if (grp == 0) {
        int cnt = end - start;
        float inv = (cnt > 0) ? (1.0f / (float)cnt) : 0.0f;
        float4 a = sm[0][lane];
        a.x *= inv; a.y *= inv; a.z *= inv; a.w *= inv;
        *(float4*)(g_concat + (size_t)g * F_CAT + lane * 4) = a;
    } else if (grp == 1) {
        float4 v = *(const float4*)(u + (size_t)g * F_U + lane * 4);
        *(float4*)(g_concat + (size_t)g * F_CAT + F_X + lane * 4) = v;
    }
}

// ---------------------------------------------------------------------------
// 3) Tiled SIMT GEMM: C[M,N] = act(A[M,K] @ B[K,N] + bias).
//    Parameterized tiles so the grid covers the chip (>=128 blocks).
//    256 threads; thread (tx,ty) computes a TMxTN micro-tile.
// ---------------------------------------------------------------------------
template <int K, int N, int BM, int BN, int TM, int TN, bool RELU>
__global__ void __launch_bounds__(256, 4) gemm_kernel(const float* __restrict__ A,
                                                      const float* __restrict__ B,
                                                      const float* __restrict__ bias,
                                                      float* __restrict__ C) {
    constexpr int BK = 16;
    constexpr int TX = BN / TN;          // threads along N
    constexpr int TY = BM / TM;          // threads along M
    static_assert(TX * TY == 256, "bad tile");
    constexpr int A_LOADS = (BM * BK) / 256;
    constexpr int B_LOADS = (BK * BN) / 256;

    __shared__ float As[BK][BM + 4];     // transposed store, padded
    __shared__ float Bs[BK][BN];

    const int bm  = blockIdx.y * BM;
    const int bn  = blockIdx.x * BN;
    const int tid = threadIdx.x;
    const int tx  = tid % TX;
    const int ty  = tid / TX;

    float acc[TM][TN] = {};

    for (int k0 = 0; k0 < K; k0 += BK) {
        #pragma unroll
        for (int i = 0; i < A_LOADS; i++) {
            int idx = tid + 256 * i;
            int row = idx / BK, col = idx % BK;
            As[col][row] = A[(size_t)(bm + row) * K + k0 + col];
        }
        #pragma unroll
        for (int i = 0; i < B_LOADS; i++) {
            int idx = tid + 256 * i;
            int row = idx / BN, col = idx % BN;
            Bs[row][col] = B[(size_t)(k0 + row) * N + bn + col];
        }
        __syncthreads();

        #pragma unroll
        for (int k = 0; k < BK; k++) {
            float a[TM], b[TN];
            #pragma unroll
            for (int i = 0; i < TM; i++) a[i] = As[k][ty * TM + i];
            #pragma unroll
            for (int j = 0; j < TN; j++) b[j] = Bs[k][tx * TN + j];
            #pragma unroll
            for (int i = 0; i < TM; i++)
                #pragma unroll
                for (int j = 0; j < TN; j++)
                    acc[i][j] = fmaf(a[i], b[j], acc[i][j]);
        }
        __syncthreads();
    }

    #pragma unroll
    for (int i = 0; i < TM; i++) {
        int row = bm + ty * TM + i;
        #pragma unroll
        for (int j = 0; j < TN; j++) {
            int col = bn + tx * TN + j;
            float v = acc[i][j] + bias[col];
            if (RELU) v = fmaxf(v, 0.0f);
            C[(size_t)row * N + col] = v;
        }
    }
}

// ---------------------------------------------------------------------------
// Launch. Inputs (metadata order): x, edge_index, edge_attr, u, batch,
//                                  W1, b1, W2, b2.  edge_* unused.
//                                  int64 inputs arrive as int32 on device.
// ---------------------------------------------------------------------------
extern "C" void kernel_launch(void* const* d_in, const int* in_sizes, int n_in,
                              void* d_out, int out_size) {
    const float* x     = (const float*)d_in[0];
    const float* u     = (const float*)d_in[3];
    const int*   batch = (const int*)d_in[4];
    const float* W1    = (const float*)d_in[5];
    const float* b1    = (const float*)d_in[6];
    const float* W2    = (const float*)d_in[7];
    const float* b2    = (const float*)d_in[8];
    float*       out   = (float*)d_out;

    void* p_concat = nullptr;
    void* p_h      = nullptr;
    cudaGetSymbolAddress(&p_concat, g_concat);  // not a stream op: capture-safe
    cudaGetSymbolAddress(&p_h, g_h);

    boundaries_kernel<<<(N_NODES + 255) / 256, 256>>>(batch);
    seg_mean_kernel<<<N_GRAPHS, 512>>>(x, u);

    // GEMM1: [1024,256] @ [256,512] -> relu -> g_h.   BM=64,BN=32 -> grid 16x16=256
    gemm_kernel<F_CAT, HIDDEN, 64, 32, 4, 2, true>
        <<<dim3(HIDDEN / 32, N_GRAPHS / 64), 256>>>(
        (const float*)p_concat, W1, b1, (float*)p_h);

    // GEMM2: [1024,512] @ [512,128] -> out.           BM=32,BN=32 -> grid 4x32=128
    gemm_kernel<HIDDEN, F_OUT, 32, 32, 2, 2, false>
        <<<dim3(F_OUT / 32, N_GRAPHS / 32), 256>>>(
        (const float*)p_h, W2, b2, out);
}